// round 13
// baseline (speedup 1.0000x reference)
#include <cuda_runtime.h>
#include <cuda_fp16.h>
#include <cstdint>

#define SEQ   2048
#define EMB   1024
#define BATCH 4
#define MTOT  (BATCH * SEQ)   // 8192

// ---------------- scratch (device globals; allocation-free) ----------------
__device__ __half g_xb  [(long long)MTOT * EMB];
__device__ __half g_Wcat[(long long)(3 * EMB) * EMB];   // [Wq;Wk;Wv]
__device__ __half g_Wob [(long long)EMB * EMB];
__device__ __half g_Qb  [(long long)MTOT * EMB];
__device__ __half g_Kb  [(long long)MTOT * EMB];
__device__ __half g_Vb  [(long long)MTOT * EMB];        // V plain [b*s][e]
__device__ __half g_Pb  [(long long)BATCH * SEQ * SEQ]; // P~ = exp(scores)
__device__ __half g_VWT [(long long)BATCH * EMB * SEQ]; // (V Wo^T)^T : [b][f][s]
__device__ float  g_Spart[(long long)MTOT * 32];        // per-row exp partial sums
__device__ float  g_inv [(long long)MTOT];              // 1/rowsum

// ---------------- helpers ----------------
__device__ __forceinline__ uint32_t smem_to_u32(const void* p) {
    uint32_t a;
    asm("{ .reg .u64 t; cvta.to.shared.u64 t, %1; cvt.u32.u64 %0, t; }" : "=r"(a) : "l"(p));
    return a;
}

#define CP_ASYNC16(dst, src) \
    asm volatile("cp.async.cg.shared.global [%0], [%1], 16;" :: "r"(dst), "l"(src))
#define CP_COMMIT() asm volatile("cp.async.commit_group;" ::: "memory")

__device__ __forceinline__ void ldmatrix_x4(uint32_t& r0, uint32_t& r1, uint32_t& r2, uint32_t& r3,
                                            uint32_t addr) {
    asm volatile("ldmatrix.sync.aligned.m8n8.x4.shared.b16 {%0,%1,%2,%3}, [%4];"
                 : "=r"(r0), "=r"(r1), "=r"(r2), "=r"(r3) : "r"(addr));
}

__device__ __forceinline__ void mma16816(float* c, uint32_t a0, uint32_t a1, uint32_t a2, uint32_t a3,
                                         uint32_t b0, uint32_t b1) {
    asm volatile("mma.sync.aligned.m16n8k16.row.col.f32.f16.f16.f32 "
                 "{%0,%1,%2,%3}, {%4,%5,%6,%7}, {%8,%9}, {%0,%1,%2,%3};"
                 : "+f"(c[0]), "+f"(c[1]), "+f"(c[2]), "+f"(c[3])
                 : "r"(a0), "r"(a1), "r"(a2), "r"(a3), "r"(b0), "r"(b1));
}

__device__ __forceinline__ uint4 pack8h(const float* v) {
    uint32_t h[4];
    #pragma unroll
    for (int i = 0; i < 4; i++) {
        __half2 hp = __halves2half2(__float2half_rn(v[2 * i]), __float2half_rn(v[2 * i + 1]));
        h[i] = *(uint32_t*)&hp;
    }
    return make_uint4(h[0], h[1], h[2], h[3]);
}

// ---------------- conversions ----------------
__global__ __launch_bounds__(256)
void cvt_flat(const float* __restrict__ in, __half* __restrict__ out)
{
    long long idx = ((long long)blockIdx.x * blockDim.x + threadIdx.x) * 8;
    const float4* src = (const float4*)(in + idx);
    float v[8];
    float4 f0 = src[0], f1 = src[1];
    v[0]=f0.x; v[1]=f0.y; v[2]=f0.z; v[3]=f0.w;
    v[4]=f1.x; v[5]=f1.y; v[6]=f1.z; v[7]=f1.w;
    *(uint4*)(out + idx) = pack8h(v);
}

__global__ __launch_bounds__(256)
void cvt_weights(const float* __restrict__ Wq, const float* __restrict__ Wk,
                 const float* __restrict__ Wv, const float* __restrict__ Wo,
                 __half* __restrict__ Wcat, __half* __restrict__ Wob)
{
    int w = blockIdx.y;
    const float* src = (w == 0) ? Wq : (w == 1) ? Wk : (w == 2) ? Wv : Wo;
    __half* dst = (w < 3) ? (Wcat + (long long)w * EMB * EMB) : Wob;
    long long idx = ((long long)blockIdx.x * blockDim.x + threadIdx.x) * 8;
    const float4* s4 = (const float4*)(src + idx);
    float v[8];
    float4 f0 = s4[0], f1 = s4[1];
    v[0]=f0.x; v[1]=f0.y; v[2]=f0.z; v[3]=f0.w;
    v[4]=f1.x; v[5]=f1.y; v[6]=f1.z; v[7]=f1.w;
    *(uint4*)(dst + idx) = pack8h(v);
}

// ---------------- rowsum inverse ----------------
__global__ __launch_bounds__(256)
void rowsum_inv(const float* __restrict__ Spart, float* __restrict__ inv)
{
    int r = blockIdx.x * blockDim.x + threadIdx.x;
    const float4* p = (const float4*)(Spart + (long long)r * 32);
    float s = 0.0f;
    #pragma unroll
    for (int i = 0; i < 8; i++) {
        float4 f = p[i];
        s += f.x + f.y + f.z + f.w;
    }
    inv[r] = 1.0f / s;
}

// ---------------- epilogue writers ----------------
__device__ __forceinline__ void write_h(__half* O, int gm, int gn, int Nl,
                                        float v0, float v1) {
    __half2 hp = __halves2half2(__float2half_rn(v0), __float2half_rn(v1));
    *(__half2*)&O[(long long)gm * Nl + gn] = hp;
}
__device__ __forceinline__ void write_hT(__half* O, int gm, int gn,
                                         float v0, float v1) {
    // O[b][n][s] with gm = b*SEQ + s, writes cols gn, gn+1
    int b = gm >> 11;
    int sdx = gm & (SEQ - 1);
    long long base = (long long)b * EMB * SEQ + (long long)gn * SEQ + sdx;
    O[base] = __float2half_rn(v0);
    O[base + SEQ] = __float2half_rn(v1);
}

// ---------------- HMMA GEMM (proven core) ----------------
// Block 128x128, BK=64, NSTAGE=3, 256 threads = 8 warps (4M x 2N), warp tile 32x64.
// EPI: 4 = fused QKV (3 regions, all plain fp16 + bias)
//      7 = final: fp32 out = inv[row]*acc + bias
#define BK      64
#define NSTAGE  3
#define STAGE_BYTES 32768
#define GEMM_SMEM (NSTAGE * STAGE_BYTES)

// shared mainloop body (A,B row-major K-wide, returns acc)
struct MainloopOut { float acc[2][8][4]; };

__device__ __forceinline__ void gemm_mainloop(
    const __half* __restrict__ A, const __half* __restrict__ B,
    int m0, int n0, int Ktot, uint32_t smem_base, int tid, int wid, int lane,
    int warp_m, int warp_n, float (&acc)[2][8][4])
{
    const int nchunks = Ktot / BK;

    auto load_stage = [&](int chunk, int s) {
        uint32_t sa = smem_base + s * STAGE_BYTES;
        uint32_t sb = sa + 16384;
        long long k0 = (long long)chunk * BK;
        #pragma unroll
        for (int t = 0; t < 4; t++) {
            int idx = tid + t * 256;
            int r = idx >> 3, c = idx & 7;
            uint32_t off = (uint32_t)((r * 8 + (c ^ (r & 7))) * 16);
            CP_ASYNC16(sa + off, (const void*)(A + (long long)(m0 + r) * Ktot + k0 + c * 8));
            CP_ASYNC16(sb + off, (const void*)(B + (long long)(n0 + r) * Ktot + k0 + c * 8));
        }
        CP_COMMIT();
    };

    #pragma unroll
    for (int mi = 0; mi < 2; mi++)
        #pragma unroll
        for (int ni = 0; ni < 8; ni++)
            #pragma unroll
            for (int r = 0; r < 4; r++)
                acc[mi][ni][r] = 0.0f;

    load_stage(0, 0);
    load_stage(1, 1);

    const int a_row = (lane & 15);
    const int a_half = lane >> 4;
    const int b_noff = (lane & 7) + ((lane & 16) ? 8 : 0);
    const int b_kg = (lane & 8) ? 1 : 0;

    for (int i = 0; i < nchunks; i++) {
        if (i + 1 < nchunks) {
            asm volatile("cp.async.wait_group 1;" ::: "memory");
        } else {
            asm volatile("cp.async.wait_group 0;" ::: "memory");
        }
        __syncthreads();

        if (i + 2 < nchunks) load_stage(i + 2, (i + 2) % NSTAGE);

        const int s = i % NSTAGE;
        const uint32_t sa = smem_base + s * STAGE_BYTES;
        const uint32_t sb = sa + 16384;

        #pragma unroll
        for (int kk = 0; kk < 4; kk++) {
            uint32_t af[2][4];
            #pragma unroll
            for (int mi = 0; mi < 2; mi++) {
                int row = warp_m * 32 + mi * 16 + a_row;
                int g = (kk * 2 + a_half) ^ (row & 7);
                ldmatrix_x4(af[mi][0], af[mi][1], af[mi][2], af[mi][3],
                            sa + (uint32_t)((row * 8 + g) * 16));
            }
            uint32_t bf[4][4];
            #pragma unroll
            for (int nt = 0; nt < 4; nt++) {
                int row = warp_n * 64 + nt * 16 + b_noff;
                int g = (kk * 2 + b_kg) ^ (row & 7);
                ldmatrix_x4(bf[nt][0], bf[nt][1], bf[nt][2], bf[nt][3],
                            sb + (uint32_t)((row * 8 + g) * 16));
            }
            #pragma unroll
            for (int mi = 0; mi < 2; mi++)
                #pragma unroll
                for (int ni = 0; ni < 8; ni++) {
                    int nt = ni >> 1;
                    uint32_t bb0 = (ni & 1) ? bf[nt][2] : bf[nt][0];
                    uint32_t bb1 = (ni & 1) ? bf[nt][3] : bf[nt][1];
                    mma16816(acc[mi][ni], af[mi][0], af[mi][1], af[mi][2], af[mi][3], bb0, bb1);
                }
        }
    }
}

// ---- QKV: x [8192,1024] x Wcat[3072,1024]^T, 3 output regions (Q,K,V plain) ----
__global__ __launch_bounds__(256, 2)
void qkv_gemm(const __half* __restrict__ A, const __half* __restrict__ B,
              const float* __restrict__ bq, const float* __restrict__ bk,
              const float* __restrict__ bv,
              __half* __restrict__ Q, __half* __restrict__ K, __half* __restrict__ V)
{
    extern __shared__ __align__(1024) char smem[];
    const uint32_t smem_base = smem_to_u32(smem);
    const int tid = threadIdx.x;
    const int wid = tid >> 5;
    const int lane = tid & 31;
    const int warp_m = wid & 3;
    const int warp_n = wid >> 2;

    const int m0 = blockIdx.y * 128;
    const int n0 = blockIdx.x * 128;

    float acc[2][8][4];
    gemm_mainloop(A, B, m0, n0, EMB, smem_base, tid, wid, lane, warp_m, warp_n, acc);

    const int rbase = m0 + warp_m * 32 + (lane >> 2);
    const int cbase = n0 + warp_n * 64 + (lane & 3) * 2;

    int region = n0 >> 10;
    const float* biasp = (region == 0) ? bq : (region == 1) ? bk : bv;
    __half* Oq = (region == 0) ? Q : (region == 1) ? K : V;

    #pragma unroll
    for (int mi = 0; mi < 2; mi++)
        #pragma unroll
        for (int ni = 0; ni < 8; ni++)
            #pragma unroll
            for (int half = 0; half < 2; half++) {
                int gm = rbase + mi * 16 + half * 8;
                int gn = cbase + ni * 8;
                int nl = gn & (EMB - 1);
                float v0 = acc[mi][ni][half * 2 + 0] + biasp[nl];
                float v1 = acc[mi][ni][half * 2 + 1] + biasp[nl + 1];
                write_h(Oq, gm, nl, EMB, v0, v1);
            }
}

// ---- combined scores(+exp) and VW = V*Wo^T (transpose write), one launch ----
// bid < 1024: scores tile; bid >= 1024: VW tile. Both K=1024.
__global__ __launch_bounds__(256, 2)
void scores_vw(const __half* __restrict__ Qb, const __half* __restrict__ Kb,
               const __half* __restrict__ Vb, const __half* __restrict__ Wob,
               __half* __restrict__ Pb, float* __restrict__ Spart,
               __half* __restrict__ VWT)
{
    extern __shared__ __align__(1024) char smem[];
    const uint32_t smem_base = smem_to_u32(smem);
    const int tid = threadIdx.x;
    const int wid = tid >> 5;
    const int lane = tid & 31;
    const int warp_m = wid & 3;
    const int warp_n = wid >> 2;

    const int bid = blockIdx.x;
    const bool is_vw = (bid >= 1024);

    const __half* A;
    const __half* B;
    int m0, n0, z = 0, xtile = 0;
    if (!is_vw) {
        z = bid >> 8;
        int rem = bid & 255;
        int y = rem >> 4;
        xtile = rem & 15;
        m0 = y * 128;
        n0 = xtile * 128;
        A = Qb + (long long)z * SEQ * EMB;
        B = Kb + (long long)z * SEQ * EMB;
    } else {
        int t = bid - 1024;
        m0 = (t >> 3) * 128;     // 0..8191 rows of V
        n0 = (t & 7) * 128;      // f cols
        A = Vb;
        B = Wob;
    }

    float acc[2][8][4];
    gemm_mainloop(A, B, m0, n0, EMB, smem_base, tid, wid, lane, warp_m, warp_n, acc);

    const int rbase = m0 + warp_m * 32 + (lane >> 2);
    const int cbase = n0 + warp_n * 64 + (lane & 3) * 2;

    if (is_vw) {
        #pragma unroll
        for (int mi = 0; mi < 2; mi++)
            #pragma unroll
            for (int ni = 0; ni < 8; ni++)
                #pragma unroll
                for (int half = 0; half < 2; half++) {
                    int gm = rbase + mi * 16 + half * 8;
                    int gn = cbase + ni * 8;
                    write_hT(VWT, gm, gn,
                             acc[mi][ni][half * 2 + 0], acc[mi][ni][half * 2 + 1]);
                }
    } else {
        const float scale = 1.0f / 32.0f;
        __half* P = Pb + (long long)z * SEQ * SEQ;
        float rs[2][2];
        rs[0][0] = rs[0][1] = rs[1][0] = rs[1][1] = 0.0f;
        #pragma unroll
        for (int mi = 0; mi < 2; mi++)
            #pragma unroll
            for (int ni = 0; ni < 8; ni++)
                #pragma unroll
                for (int half = 0; half < 2; half++) {
                    int gm = rbase + mi * 16 + half * 8;
                    int gn = cbase + ni * 8;
                    float e0 = __expf(acc[mi][ni][half * 2 + 0] * scale);
                    float e1 = __expf(acc[mi][ni][half * 2 + 1] * scale);
                    write_h(P, gm, gn, SEQ, e0, e1);
                    rs[mi][half] += e0 + e1;
                }
        // reduce the 4 lanes sharing each row
        #pragma unroll
        for (int mi = 0; mi < 2; mi++)
            #pragma unroll
            for (int hf = 0; hf < 2; hf++) {
                float r = rs[mi][hf];
                r += __shfl_xor_sync(0xffffffffu, r, 1);
                r += __shfl_xor_sync(0xffffffffu, r, 2);
                if ((lane & 3) == 0) {
                    int gm = rbase + mi * 16 + hf * 8;
                    long long rrow = (long long)z * SEQ + gm;
                    Spart[rrow * 32 + xtile * 2 + warp_n] = r;
                }
            }
    }
}

// ---- final: out[b][q][f] = inv[b*SEQ+q] * (P~ . VWT) + bo[f]  (fp32) ----
__global__ __launch_bounds__(256, 2)
void final_gemm(const __half* __restrict__ Pb, const __half* __restrict__ VWT,
                const float* __restrict__ inv, const float* __restrict__ bo,
                float* __restrict__ Out)
{
    extern __shared__ __align__(1024) char smem[];
    const uint32_t smem_base = smem_to_u32(smem);
    const int tid = threadIdx.x;
    const int wid = tid >> 5;
    const int lane = tid & 31;
    const int warp_m = wid & 3;
    const int warp_n = wid >> 2;

    const int z = blockIdx.z;
    const __half* A = Pb + (long long)z * SEQ * SEQ;
    const __half* B = VWT + (long long)z * EMB * SEQ;
    float* O = Out + (long long)z * SEQ * EMB;

    const int m0 = blockIdx.y * 128;
    const int n0 = blockIdx.x * 128;

    float acc[2][8][4];
    gemm_mainloop(A, B, m0, n0, SEQ, smem_base, tid, wid, lane, warp_m, warp_n, acc);

    const int rbase = m0 + warp_m * 32 + (lane >> 2);
    const int cbase = n0 + warp_n * 64 + (lane & 3) * 2;

    #pragma unroll
    for (int mi = 0; mi < 2; mi++)
        #pragma unroll
        for (int ni = 0; ni < 8; ni++)
            #pragma unroll
            for (int half = 0; half < 2; half++) {
                int gm = rbase + mi * 16 + half * 8;
                int gn = cbase + ni * 8;
                float iv = inv[(long long)z * SEQ + gm];
                float v0 = acc[mi][ni][half * 2 + 0] * iv + bo[gn];
                float v1 = acc[mi][ni][half * 2 + 1] * iv + bo[gn + 1];
                *(float2*)&O[(long long)gm * EMB + gn] = make_float2(v0, v1);
            }
}

// ---------------- launch ----------------
extern "C" void kernel_launch(void* const* d_in, const int* in_sizes, int n_in,
                              void* d_out, int out_size)
{
    const float* x  = (const float*)d_in[0];
    const float* Wq = (const float*)d_in[1];
    const float* bq = (const float*)d_in[2];
    const float* Wk = (const float*)d_in[3];
    const float* bk = (const float*)d_in[4];
    const float* Wv = (const float*)d_in[5];
    const float* bv = (const float*)d_in[6];
    const float* Wo = (const float*)d_in[7];
    const float* bo = (const float*)d_in[8];
    float* out = (float*)d_out;

    __half *xb, *Wcat, *Wob, *Qb, *Kb, *Vb, *Pb, *VWT;
    float *Spart, *inv;
    cudaGetSymbolAddress((void**)&xb,    g_xb);
    cudaGetSymbolAddress((void**)&Wcat,  g_Wcat);
    cudaGetSymbolAddress((void**)&Wob,   g_Wob);
    cudaGetSymbolAddress((void**)&Qb,    g_Qb);
    cudaGetSymbolAddress((void**)&Kb,    g_Kb);
    cudaGetSymbolAddress((void**)&Vb,    g_Vb);
    cudaGetSymbolAddress((void**)&Pb,    g_Pb);
    cudaGetSymbolAddress((void**)&VWT,   g_VWT);
    cudaGetSymbolAddress((void**)&Spart, g_Spart);
    cudaGetSymbolAddress((void**)&inv,   g_inv);

    cudaFuncSetAttribute(qkv_gemm,   cudaFuncAttributeMaxDynamicSharedMemorySize, GEMM_SMEM);
    cudaFuncSetAttribute(scores_vw,  cudaFuncAttributeMaxDynamicSharedMemorySize, GEMM_SMEM);
    cudaFuncSetAttribute(final_gemm, cudaFuncAttributeMaxDynamicSharedMemorySize, GEMM_SMEM);

    // 1) conversions
    cvt_flat<<<(unsigned)(((long long)MTOT * EMB / 8) / 256), 256>>>(x, xb);
    {
        dim3 gw((unsigned)(((long long)EMB * EMB / 8) / 256), 4);
        cvt_weights<<<gw, 256>>>(Wq, Wk, Wv, Wo, Wcat, Wob);
    }

    // 2) fused QKV projection: grid (24, 64)
    dim3 gQKV(3 * EMB / 128, MTOT / 128, 1);
    qkv_gemm<<<gQKV, 256, GEMM_SMEM>>>(xb, Wcat, bq, bk, bv, Qb, Kb, Vb);

    // 3) combined: scores+exp (1024 tiles) and VW = V*Wo^T (512 tiles)
    scores_vw<<<1536, 256, GEMM_SMEM>>>(Qb, Kb, Vb, Wob, Pb, Spart, VWT);

    // 4) inv[row] = 1 / rowsum
    rowsum_inv<<<MTOT / 256, 256>>>(Spart, inv);

    // 5) final: out = inv * (P~ . VWT) + bo
    dim3 gF(EMB / 128, SEQ / 128, BATCH);
    final_gemm<<<gF, 256, GEMM_SMEM>>>(Pb, VWT, inv, bo, out);
}

// round 15
// speedup vs baseline: 1.0594x; 1.0594x over previous
#include <cuda_runtime.h>
#include <cuda_fp16.h>
#include <cstdint>

#define SEQ   2048
#define EMB   1024
#define BATCH 4
#define MTOT  (BATCH * SEQ)   // 8192

// ---------------- scratch (device globals; allocation-free) ----------------
__device__ __half g_xb [(long long)MTOT * EMB];
__device__ __half g_WqT[(long long)EMB * EMB];          // Wq^T fp16
__device__ __half g_WkT[(long long)EMB * EMB];          // Wk^T
__device__ __half g_WvT[(long long)EMB * EMB];          // Wv^T
__device__ __half g_Wo [(long long)EMB * EMB];          // Wo (plain)
__device__ __half g_H  [(long long)EMB * EMB];          // H = Wk^T·Wq
__device__ __half g_G  [(long long)EMB * EMB];          // G = Wo·Wv
__device__ float  g_wu [EMB];                           // Wq^T·bk
__device__ float  g_wv [EMB];                           // Wk^T·bq
__device__ float  g_w2 [EMB];                           // Wo·bv
__device__ float  g_c  [1];                             // bq·bk
__device__ float  g_su [MTOT];                          // scale*(x·wu + c)
__device__ float  g_sv [MTOT];                          // scale*(x·wv)
__device__ __half g_T  [(long long)MTOT * EMB];         // T = x·H^T
__device__ __half g_VWT[(long long)BATCH * EMB * SEQ];  // (V·Wo^T)^T : [b][f][s]
__device__ __half g_Pb [(long long)BATCH * SEQ * SEQ];  // P~ = exp(scores)
__device__ float  g_Spart[(long long)MTOT * 32];
__device__ float  g_inv[MTOT];

// ---------------- helpers ----------------
__device__ __forceinline__ uint32_t smem_to_u32(const void* p) {
    uint32_t a;
    asm("{ .reg .u64 t; cvta.to.shared.u64 t, %1; cvt.u32.u64 %0, t; }" : "=r"(a) : "l"(p));
    return a;
}

#define CP_ASYNC16(dst, src) \
    asm volatile("cp.async.cg.shared.global [%0], [%1], 16;" :: "r"(dst), "l"(src))
#define CP_COMMIT() asm volatile("cp.async.commit_group;" ::: "memory")

__device__ __forceinline__ void ldmatrix_x4(uint32_t& r0, uint32_t& r1, uint32_t& r2, uint32_t& r3,
                                            uint32_t addr) {
    asm volatile("ldmatrix.sync.aligned.m8n8.x4.shared.b16 {%0,%1,%2,%3}, [%4];"
                 : "=r"(r0), "=r"(r1), "=r"(r2), "=r"(r3) : "r"(addr));
}

__device__ __forceinline__ void mma16816(float* c, uint32_t a0, uint32_t a1, uint32_t a2, uint32_t a3,
                                         uint32_t b0, uint32_t b1) {
    asm volatile("mma.sync.aligned.m16n8k16.row.col.f32.f16.f16.f32 "
                 "{%0,%1,%2,%3}, {%4,%5,%6,%7}, {%8,%9}, {%0,%1,%2,%3};"
                 : "+f"(c[0]), "+f"(c[1]), "+f"(c[2]), "+f"(c[3])
                 : "r"(a0), "r"(a1), "r"(a2), "r"(a3), "r"(b0), "r"(b1));
}

__device__ __forceinline__ uint4 pack8h(const float* v) {
    uint32_t h[4];
    #pragma unroll
    for (int i = 0; i < 4; i++) {
        __half2 hp = __halves2half2(__float2half_rn(v[2 * i]), __float2half_rn(v[2 * i + 1]));
        h[i] = *(uint32_t*)&hp;
    }
    return make_uint4(h[0], h[1], h[2], h[3]);
}

// ---------------- conversions ----------------
__global__ __launch_bounds__(256)
void cvt_x(const float* __restrict__ in, __half* __restrict__ out)
{
    long long idx = ((long long)blockIdx.x * blockDim.x + threadIdx.x) * 8;
    const float4* src = (const float4*)(in + idx);
    float v[8];
    float4 f0 = src[0], f1 = src[1];
    v[0]=f0.x; v[1]=f0.y; v[2]=f0.z; v[3]=f0.w;
    v[4]=f1.x; v[5]=f1.y; v[6]=f1.z; v[7]=f1.w;
    *(uint4*)(out + idx) = pack8h(v);
}

// transpose-convert Wq,Wk,Wv (w=0,1,2) and straight-convert Wo (w=3)
__global__ void cvt_wt(const float* __restrict__ Wq, const float* __restrict__ Wk,
                       const float* __restrict__ Wv, const float* __restrict__ Wo,
                       __half* __restrict__ WqT, __half* __restrict__ WkT,
                       __half* __restrict__ WvT, __half* __restrict__ Woh)
{
    int w = blockIdx.z;
    const float* src = (w == 0) ? Wq : (w == 1) ? Wk : (w == 2) ? Wv : Wo;
    __half* dst = (w == 0) ? WqT : (w == 1) ? WkT : (w == 2) ? WvT : Woh;
    int r0 = blockIdx.y * 32;
    int c0 = blockIdx.x * 32;
    int tx = threadIdx.x, ty = threadIdx.y;   // 32 x 8

    if (w == 3) {
        #pragma unroll
        for (int k = 0; k < 4; k++) {
            int f = r0 + ty + k * 8;
            dst[(long long)f * EMB + c0 + tx] = __float2half_rn(src[(long long)f * EMB + c0 + tx]);
        }
        return;
    }
    __shared__ __half sm[32][36];
    #pragma unroll
    for (int k = 0; k < 4; k++) {
        int f = r0 + ty + k * 8;
        sm[tx][ty + k * 8] = __float2half_rn(src[(long long)f * EMB + c0 + tx]);
    }
    __syncthreads();
    #pragma unroll
    for (int k = 0; k < 4; k++) {
        int e = c0 + ty + k * 8;
        dst[(long long)e * EMB + r0 + tx] = sm[ty + k * 8][tx];
    }
}

// vec precomputes: y=0 wu, y=1 wv, y=2 (bid.x==0) c; y=3 w2
__global__ __launch_bounds__(256)
void vec_kernel(const float* __restrict__ Wq, const float* __restrict__ Wk,
                const float* __restrict__ Wo,
                const float* __restrict__ bq, const float* __restrict__ bk,
                const float* __restrict__ bv,
                float* __restrict__ wu, float* __restrict__ wv,
                float* __restrict__ w2, float* __restrict__ cc)
{
    int y = blockIdx.y;
    int tid = threadIdx.x;
    if (y == 0 || y == 1) {
        int e = blockIdx.x * 256 + tid;
        if (e >= EMB) return;               // <-- FIX: bounds guard
        const float* W = (y == 0) ? Wq : Wk;
        const float* b = (y == 0) ? bk : bq;
        float* o = (y == 0) ? wu : wv;
        float s = 0.0f;
        for (int f = 0; f < EMB; f++)
            s += W[(long long)f * EMB + e] * b[f];
        o[e] = s;
    } else if (y == 2) {
        if (blockIdx.x != 0) return;
        __shared__ float red[256];
        float s = 0.0f;
        for (int f = tid; f < EMB; f += 256) s += bq[f] * bk[f];
        red[tid] = s;
        __syncthreads();
        for (int o = 128; o > 0; o >>= 1) {
            if (tid < o) red[tid] += red[tid + o];
            __syncthreads();
        }
        if (tid == 0) cc[0] = red[0];
    } else {
        int f = blockIdx.x * 32 + (tid >> 3);
        int seg = tid & 7;
        const float* row = Wo + (long long)f * EMB + seg * 128;
        float s = 0.0f;
        #pragma unroll
        for (int g = 0; g < 128; g++) s += row[g] * bv[seg * 128 + g];
        s += __shfl_xor_sync(0xffffffffu, s, 1);
        s += __shfl_xor_sync(0xffffffffu, s, 2);
        s += __shfl_xor_sync(0xffffffffu, s, 4);
        if (seg == 0) w2[f] = s;
    }
}

// su[i] = scale*(x[i]·wu + c), sv[i] = scale*(x[i]·wv) — warp per row
__global__ __launch_bounds__(256)
void uv_kernel(const __half* __restrict__ xb, const float* __restrict__ wu,
               const float* __restrict__ wv, const float* __restrict__ cc,
               float* __restrict__ su, float* __restrict__ sv)
{
    const float scale = 1.0f / 32.0f;
    int wid = threadIdx.x >> 5;
    int lane = threadIdx.x & 31;
    long long row = (long long)blockIdx.x * 8 + wid;
    const __half* xr = xb + row * EMB;
    float du = 0.0f, dv = 0.0f;
    #pragma unroll
    for (int k = 0; k < 32; k++) {
        int e = k * 32 + lane;
        float xv = __half2float(xr[e]);
        du += xv * wu[e];
        dv += xv * wv[e];
    }
    #pragma unroll
    for (int o = 16; o > 0; o >>= 1) {
        du += __shfl_xor_sync(0xffffffffu, du, o);
        dv += __shfl_xor_sync(0xffffffffu, dv, o);
    }
    if (lane == 0) {
        su[row] = scale * (du + cc[0]);
        sv[row] = scale * dv;
    }
}

// ---------------- rowsum inverse ----------------
__global__ __launch_bounds__(256)
void rowsum_inv(const float* __restrict__ Spart, float* __restrict__ inv)
{
    int r = blockIdx.x * blockDim.x + threadIdx.x;
    const float4* p = (const float4*)(Spart + (long long)r * 32);
    float s = 0.0f;
    #pragma unroll
    for (int i = 0; i < 8; i++) {
        float4 f = p[i];
        s += f.x + f.y + f.z + f.w;
    }
    inv[r] = 1.0f / s;
}

// ---------------- epilogue writers ----------------
__device__ __forceinline__ void write_h(__half* O, int gm, int gn, int Nl,
                                        float v0, float v1) {
    __half2 hp = __halves2half2(__float2half_rn(v0), __float2half_rn(v1));
    *(__half2*)&O[(long long)gm * Nl + gn] = hp;
}
__device__ __forceinline__ void write_hT(__half* O, int gm, int gn,
                                         float v0, float v1) {
    int b = gm >> 11;
    int sdx = gm & (SEQ - 1);
    long long base = (long long)b * EMB * SEQ + (long long)gn * SEQ + sdx;
    O[base] = __float2half_rn(v0);
    O[base + SEQ] = __float2half_rn(v1);
}

// ---------------- HMMA mainloop (proven core) ----------------
#define BK      64
#define NSTAGE  3
#define STAGE_BYTES 32768
#define GEMM_SMEM (NSTAGE * STAGE_BYTES)

__device__ __forceinline__ void gemm_mainloop(
    const __half* __restrict__ A, const __half* __restrict__ B,
    int m0, int n0, int Ktot, uint32_t smem_base, int tid, int lane,
    int warp_m, int warp_n, float (&acc)[2][8][4])
{
    const int nchunks = Ktot / BK;

    auto load_stage = [&](int chunk, int s) {
        uint32_t sa = smem_base + s * STAGE_BYTES;
        uint32_t sb = sa + 16384;
        long long k0 = (long long)chunk * BK;
        #pragma unroll
        for (int t = 0; t < 4; t++) {
            int idx = tid + t * 256;
            int r = idx >> 3, c = idx & 7;
            uint32_t off = (uint32_t)((r * 8 + (c ^ (r & 7))) * 16);
            CP_ASYNC16(sa + off, (const void*)(A + (long long)(m0 + r) * Ktot + k0 + c * 8));
            CP_ASYNC16(sb + off, (const void*)(B + (long long)(n0 + r) * Ktot + k0 + c * 8));
        }
        CP_COMMIT();
    };

    #pragma unroll
    for (int mi = 0; mi < 2; mi++)
        #pragma unroll
        for (int ni = 0; ni < 8; ni++)
            #pragma unroll
            for (int r = 0; r < 4; r++)
                acc[mi][ni][r] = 0.0f;

    load_stage(0, 0);
    load_stage(1, 1);

    const int a_row = (lane & 15);
    const int a_half = lane >> 4;
    const int b_noff = (lane & 7) + ((lane & 16) ? 8 : 0);
    const int b_kg = (lane & 8) ? 1 : 0;

    for (int i = 0; i < nchunks; i++) {
        if (i + 1 < nchunks) {
            asm volatile("cp.async.wait_group 1;" ::: "memory");
        } else {
            asm volatile("cp.async.wait_group 0;" ::: "memory");
        }
        __syncthreads();

        if (i + 2 < nchunks) load_stage(i + 2, (i + 2) % NSTAGE);

        const int s = i % NSTAGE;
        const uint32_t sa = smem_base + s * STAGE_BYTES;
        const uint32_t sb = sa + 16384;

        #pragma unroll
        for (int kk = 0; kk < 4; kk++) {
            uint32_t af[2][4];
            #pragma unroll
            for (int mi = 0; mi < 2; mi++) {
                int row = warp_m * 32 + mi * 16 + a_row;
                int g = (kk * 2 + a_half) ^ (row & 7);
                ldmatrix_x4(af[mi][0], af[mi][1], af[mi][2], af[mi][3],
                            sa + (uint32_t)((row * 8 + g) * 16));
            }
            uint32_t bf[4][4];
            #pragma unroll
            for (int nt = 0; nt < 4; nt++) {
                int row = warp_n * 64 + nt * 16 + b_noff;
                int g = (kk * 2 + b_kg) ^ (row & 7);
                ldmatrix_x4(bf[nt][0], bf[nt][1], bf[nt][2], bf[nt][3],
                            sb + (uint32_t)((row * 8 + g) * 16));
            }
            #pragma unroll
            for (int mi = 0; mi < 2; mi++)
                #pragma unroll
                for (int ni = 0; ni < 8; ni++) {
                    int nt = ni >> 1;
                    uint32_t bb0 = (ni & 1) ? bf[nt][2] : bf[nt][0];
                    uint32_t bb1 = (ni & 1) ? bf[nt][3] : bf[nt][1];
                    mma16816(acc[mi][ni], af[mi][0], af[mi][1], af[mi][2], af[mi][3], bb0, bb1);
                }
        }
    }
}

// ---- H = Wk^T·Wq (64 tiles), G = Wo·Wv (64 tiles), one launch ----
__global__ __launch_bounds__(256, 2)
void hg_gemm(const __half* __restrict__ WkT, const __half* __restrict__ WqT,
             const __half* __restrict__ Wo, const __half* __restrict__ WvT,
             __half* __restrict__ H, __half* __restrict__ G)
{
    extern __shared__ __align__(1024) char smem[];
    const uint32_t smem_base = smem_to_u32(smem);
    const int tid = threadIdx.x;
    const int wid = tid >> 5;
    const int lane = tid & 31;
    const int warp_m = wid & 3;
    const int warp_n = wid >> 2;

    int bid = blockIdx.x;
    bool isG = (bid >= 64);
    int t = isG ? bid - 64 : bid;
    int m0 = (t >> 3) * 128;
    int n0 = (t & 7) * 128;
    const __half* A = isG ? Wo : WkT;
    const __half* B = isG ? WvT : WqT;
    __half* O = isG ? G : H;

    float acc[2][8][4];
    gemm_mainloop(A, B, m0, n0, EMB, smem_base, tid, lane, warp_m, warp_n, acc);

    const int rbase = m0 + warp_m * 32 + (lane >> 2);
    const int cbase = n0 + warp_n * 64 + (lane & 3) * 2;
    #pragma unroll
    for (int mi = 0; mi < 2; mi++)
        #pragma unroll
        for (int ni = 0; ni < 8; ni++)
            #pragma unroll
            for (int half = 0; half < 2; half++) {
                int gm = rbase + mi * 16 + half * 8;
                int gn = cbase + ni * 8;
                write_h(O, gm, gn, EMB, acc[mi][ni][half * 2 + 0], acc[mi][ni][half * 2 + 1]);
            }
}

// ---- merged: T = x H^T (512 tiles) and VW^T (512 tiles) ----
__global__ __launch_bounds__(256, 2)
void tvw_gemm(const __half* __restrict__ xb, const __half* __restrict__ H,
              const __half* __restrict__ G, const float* __restrict__ w2,
              __half* __restrict__ T, __half* __restrict__ VWT)
{
    extern __shared__ __align__(1024) char smem[];
    const uint32_t smem_base = smem_to_u32(smem);
    const int tid = threadIdx.x;
    const int wid = tid >> 5;
    const int lane = tid & 31;
    const int warp_m = wid & 3;
    const int warp_n = wid >> 2;

    int bid = blockIdx.x;
    bool isVW = (bid >= 512);
    int t = isVW ? bid - 512 : bid;
    int m0 = (t >> 3) * 128;
    int n0 = (t & 7) * 128;
    const __half* B = isVW ? G : H;

    float acc[2][8][4];
    gemm_mainloop(xb, B, m0, n0, EMB, smem_base, tid, lane, warp_m, warp_n, acc);

    const int rbase = m0 + warp_m * 32 + (lane >> 2);
    const int cbase = n0 + warp_n * 64 + (lane & 3) * 2;
    #pragma unroll
    for (int mi = 0; mi < 2; mi++)
        #pragma unroll
        for (int ni = 0; ni < 8; ni++)
            #pragma unroll
            for (int half = 0; half < 2; half++) {
                int gm = rbase + mi * 16 + half * 8;
                int gn = cbase + ni * 8;
                float v0 = acc[mi][ni][half * 2 + 0];
                float v1 = acc[mi][ni][half * 2 + 1];
                if (isVW) {
                    v0 += w2[gn]; v1 += w2[gn + 1];
                    write_hT(VWT, gm, gn, v0, v1);
                } else {
                    write_h(T, gm, gn, EMB, v0, v1);
                }
            }
}

// ---- scores: P~ = exp(scale*T x^T + su + sv), partial row sums ----
__global__ __launch_bounds__(256, 2)
void scores_gemm(const __half* __restrict__ T, const __half* __restrict__ xb,
                 const float* __restrict__ su, const float* __restrict__ sv,
                 __half* __restrict__ Pb, float* __restrict__ Spart)
{
    extern __shared__ __align__(1024) char smem[];
    const uint32_t smem_base = smem_to_u32(smem);
    const int tid = threadIdx.x;
    const int wid = tid >> 5;
    const int lane = tid & 31;
    const int warp_m = wid & 3;
    const int warp_n = wid >> 2;

    int bid = blockIdx.x;
    int z = bid >> 8;
    int rem = bid & 255;
    int y = rem >> 4;
    int xt = rem & 15;
    int m0 = y * 128;
    int n0 = xt * 128;
    const __half* A = T + (long long)z * SEQ * EMB;
    const __half* B = xb + (long long)z * SEQ * EMB;
    __half* P = Pb + (long long)z * SEQ * SEQ;

    float acc[2][8][4];
    gemm_mainloop(A, B, m0, n0, EMB, smem_base, tid, lane, warp_m, warp_n, acc);

    const float scale = 1.0f / 32.0f;
    const int rbase = m0 + warp_m * 32 + (lane >> 2);
    const int cbase = n0 + warp_n * 64 + (lane & 3) * 2;

    float rs[2][2];
    rs[0][0] = rs[0][1] = rs[1][0] = rs[1][1] = 0.0f;

    #pragma unroll
    for (int mi = 0; mi < 2; mi++)
        #pragma unroll
        for (int half = 0; half < 2; half++) {
            int gm = rbase + mi * 16 + half * 8;
            float rowadd = su[(long long)z * SEQ + gm];
            #pragma unroll
            for (int ni = 0; ni < 8; ni++) {
                int gn = cbase + ni * 8;
                float c0 = sv[(long long)z * SEQ + gn];
                float c1 = sv[(long long)z * SEQ + gn + 1];
                float e0 = __expf(acc[mi][ni][half * 2 + 0] * scale + rowadd + c0);
                float e1 = __expf(acc[mi][ni][half * 2 + 1] * scale + rowadd + c1);
                write_h(P, gm, gn, SEQ, e0, e1);
                rs[mi][half] += e0 + e1;
            }
        }

    #pragma unroll
    for (int mi = 0; mi < 2; mi++)
        #pragma unroll
        for (int hf = 0; hf < 2; hf++) {
            float r = rs[mi][hf];
            r += __shfl_xor_sync(0xffffffffu, r, 1);
            r += __shfl_xor_sync(0xffffffffu, r, 2);
            if ((lane & 3) == 0) {
                int gm = rbase + mi * 16 + hf * 8;
                long long rrow = (long long)z * SEQ + gm;
                Spart[rrow * 32 + xt * 2 + warp_n] = r;
            }
        }
}

// ---- final: out = inv[row]*(P~ . VWT) + bo  (fp32, K=2048) ----
__global__ __launch_bounds__(256, 2)
void final_gemm(const __half* __restrict__ Pb, const __half* __restrict__ VWT,
                const float* __restrict__ inv, const float* __restrict__ bo,
                float* __restrict__ Out)
{
    extern __shared__ __align__(1024) char smem[];
    const uint32_t smem_base = smem_to_u32(smem);
    const int tid = threadIdx.x;
    const int wid = tid >> 5;
    const int lane = tid & 31;
    const int warp_m = wid & 3;
    const int warp_n = wid >> 2;

    const int z = blockIdx.z;
    const __half* A = Pb + (long long)z * SEQ * SEQ;
    const __half* B = VWT + (long long)z * EMB * SEQ;
    float* O = Out + (long long)z * SEQ * EMB;

    const int m0 = blockIdx.y * 128;
    const int n0 = blockIdx.x * 128;

    float acc[2][8][4];
    gemm_mainloop(A, B, m0, n0, SEQ, smem_base, tid, lane, warp_m, warp_n, acc);

    const int rbase = m0 + warp_m * 32 + (lane >> 2);
    const int cbase = n0 + warp_n * 64 + (lane & 3) * 2;

    #pragma unroll
    for (int mi = 0; mi < 2; mi++)
        #pragma unroll
        for (int ni = 0; ni < 8; ni++)
            #pragma unroll
            for (int half = 0; half < 2; half++) {
                int gm = rbase + mi * 16 + half * 8;
                int gn = cbase + ni * 8;
                float iv = inv[(long long)z * SEQ + gm];
                float v0 = acc[mi][ni][half * 2 + 0] * iv + bo[gn];
                float v1 = acc[mi][ni][half * 2 + 1] * iv + bo[gn + 1];
                *(float2*)&O[(long long)gm * EMB + gn] = make_float2(v0, v1);
            }
}

// ---------------- launch ----------------
extern "C" void kernel_launch(void* const* d_in, const int* in_sizes, int n_in,
                              void* d_out, int out_size)
{
    const float* x  = (const float*)d_in[0];
    const float* Wq = (const float*)d_in[1];
    const float* bq = (const float*)d_in[2];
    const float* Wk = (const float*)d_in[3];
    const float* bk = (const float*)d_in[4];
    const float* Wv = (const float*)d_in[5];
    const float* bv = (const float*)d_in[6];
    const float* Wo = (const float*)d_in[7];
    const float* bo = (const float*)d_in[8];
    float* out = (float*)d_out;

    __half *xb, *WqT, *WkT, *WvT, *Woh, *H, *G, *T, *VWT, *Pb;
    float *wu, *wv, *w2, *cc, *su, *sv, *Spart, *inv;
    cudaGetSymbolAddress((void**)&xb,  g_xb);
    cudaGetSymbolAddress((void**)&WqT, g_WqT);
    cudaGetSymbolAddress((void**)&WkT, g_WkT);
    cudaGetSymbolAddress((void**)&WvT, g_WvT);
    cudaGetSymbolAddress((void**)&Woh, g_Wo);
    cudaGetSymbolAddress((void**)&H,   g_H);
    cudaGetSymbolAddress((void**)&G,   g_G);
    cudaGetSymbolAddress((void**)&T,   g_T);
    cudaGetSymbolAddress((void**)&VWT, g_VWT);
    cudaGetSymbolAddress((void**)&Pb,  g_Pb);
    cudaGetSymbolAddress((void**)&wu,  g_wu);
    cudaGetSymbolAddress((void**)&wv,  g_wv);
    cudaGetSymbolAddress((void**)&w2,  g_w2);
    cudaGetSymbolAddress((void**)&cc,  g_c);
    cudaGetSymbolAddress((void**)&su,  g_su);
    cudaGetSymbolAddress((void**)&sv,  g_sv);
    cudaGetSymbolAddress((void**)&Spart, g_Spart);
    cudaGetSymbolAddress((void**)&inv, g_inv);

    cudaFuncSetAttribute(hg_gemm,     cudaFuncAttributeMaxDynamicSharedMemorySize, GEMM_SMEM);
    cudaFuncSetAttribute(tvw_gemm,    cudaFuncAttributeMaxDynamicSharedMemorySize, GEMM_SMEM);
    cudaFuncSetAttribute(scores_gemm, cudaFuncAttributeMaxDynamicSharedMemorySize, GEMM_SMEM);
    cudaFuncSetAttribute(final_gemm,  cudaFuncAttributeMaxDynamicSharedMemorySize, GEMM_SMEM);

    // 1) conversions + tiny precomputes
    cvt_x<<<(unsigned)(((long long)MTOT * EMB / 8) / 256), 256>>>(x, xb);
    {
        dim3 g(32, 32, 4), b(32, 8);
        cvt_wt<<<g, b>>>(Wq, Wk, Wv, Wo, WqT, WkT, WvT, Woh);
    }
    {
        dim3 g(32, 4);
        vec_kernel<<<g, 256>>>(Wq, Wk, Wo, bq, bk, bv, wu, wv, w2, cc);
    }
    uv_kernel<<<MTOT / 8, 256>>>(xb, wu, wv, cc, su, sv);

    // 2) H and G
    hg_gemm<<<128, 256, GEMM_SMEM>>>(WkT, WqT, Woh, WvT, H, G);

    // 3) merged T = x H^T and VW^T = (x G^T + w2)^T
    tvw_gemm<<<1024, 256, GEMM_SMEM>>>(xb, H, G, w2, T, VWT);

    // 4) scores + exp + partial sums
    scores_gemm<<<1024, 256, GEMM_SMEM>>>(T, xb, su, sv, Pb, Spart);

    // 5) inv
    rowsum_inv<<<MTOT / 256, 256>>>(Spart, inv);

    // 6) final
    dim3 gF(EMB / 128, SEQ / 128, BATCH);
    final_gemm<<<gF, 256, GEMM_SMEM>>>(Pb, VWT, inv, bo, out);
}